// round 8
// baseline (speedup 1.0000x reference)
#include <cuda_runtime.h>
#include <math.h>

#define EPS 1e-5f
#define TS 8
#define HALO 14          // TS + 6
#define PSTR 68          // per-pixel channel stride in floats (64 + 4 pad)
#define NHALO 196        // 14*14
#define TSTR 20          // ts row stride (16 + 4 pad)
#define PPSTR 132        // packed pair row stride in floats (64 ch * 2 + 4 pad; 528B, 16B-chunk conflict-free)

// smem layout (floats)
#define OFF_XS   0
#define OFF_TS   (OFF_XS   + NHALO * PSTR)     // 13328
#define OFF_INVP (OFF_TS   + 64 * TSTR)        // +1280
#define OFF_X1P  (OFF_INVP + 64 * PSTR)        // +4352
#define OFF_X0P  (OFF_X1P  + 32 * PPSTR)       // +4224
#define OFF_WRS  (OFF_X0P  + 32 * PPSTR)       // +4224
#define OFF_WSPT (OFF_WRS  + 1024)
#define OFF_BSPS (OFF_WSPT + 4 * 16 * 52)      // +3328
#define OFF_WCS  (OFF_BSPS + 4 * 52)           // +208
#define OFF_WMS  (OFF_WCS  + 128 * PSTR)       // +8704
#define OFF_BVS  (OFF_WMS  + 128 * PSTR)       // +8704
#define SMEM_FLOATS (OFF_BVS + 128)
#define SMEM_BYTES (SMEM_FLOATS * 4)           // 198,016 B

typedef unsigned long long u64;

__device__ __forceinline__ u64 pk2(float lo, float hi) {
    u64 r; asm("mov.b64 %0,{%1,%2};" : "=l"(r) : "f"(lo), "f"(hi)); return r;
}
__device__ __forceinline__ u64 dup2f(float v) { return pk2(v, v); }
__device__ __forceinline__ void unpk2(u64 a, float& x, float& y) {
    asm("mov.b64 {%0,%1},%2;" : "=f"(x), "=f"(y) : "l"(a));
}
__device__ __forceinline__ void fma2(u64& d, u64 a, u64 b) {
    asm("fma.rn.f32x2 %0,%1,%2,%0;" : "+l"(d) : "l"(a), "l"(b));
}
__device__ __forceinline__ u64 add2(u64 a, u64 b) {
    u64 r; asm("add.rn.f32x2 %0,%1,%2;" : "=l"(r) : "l"(a), "l"(b)); return r;
}

__device__ __forceinline__ float dot4acc(float4 w, float4 v, float a) {
    a = fmaf(w.x, v.x, a);
    a = fmaf(w.y, v.y, a);
    a = fmaf(w.z, v.z, a);
    a = fmaf(w.w, v.w, a);
    return a;
}

__device__ __forceinline__ float gelu_exact(float v) {
    return 0.5f * v * (1.0f + erff(v * 0.70710678118654752f));
}

// Packed partial involution over kernel taps [KB, KB+NKK).
// Builds the kern slice with f32x2 accumulation, then accumulates the partial
// involution for all 16 channels of group q into 8 packed accumulators.
template<int KB, int NKK>
__device__ __forceinline__ void inv_partial(
    const float* __restrict__ wspT, const float* __restrict__ bsps,
    const float* __restrict__ ts, const float* __restrict__ xs,
    int p, int q, int py, int px, u64* inv2)
{
    constexpr int NKP = ((NKK + 3) / 4) * 2;   // packed u64 count (even)
    u64 kern2[NKP];

    const ulonglong2* b2 = (const ulonglong2*)(bsps + q * 52 + KB);
    #pragma unroll
    for (int j = 0; j < NKP / 2; j++) {
        ulonglong2 v = b2[j];
        kern2[2 * j] = v.x; kern2[2 * j + 1] = v.y;
    }

    const float4* t4 = (const float4*)(ts + p * TSTR);
    #pragma unroll
    for (int r4 = 0; r4 < 4; r4++) {
        float4 tv = t4[r4];
        float tvals[4] = {tv.x, tv.y, tv.z, tv.w};
        #pragma unroll
        for (int rj = 0; rj < 4; rj++) {
            int r = r4 * 4 + rj;
            u64 td = dup2f(tvals[rj]);
            const ulonglong2* w2 = (const ulonglong2*)(wspT + (q * 16 + r) * 52 + KB);
            #pragma unroll
            for (int j = 0; j < NKP / 2; j++) {
                ulonglong2 wv = w2[j];
                fma2(kern2[2 * j],     td, wv.x);
                fma2(kern2[2 * j + 1], td, wv.y);
            }
        }
    }

    float kf[NKP * 2];
    #pragma unroll
    for (int j = 0; j < NKP; j++) unpk2(kern2[j], kf[2 * j], kf[2 * j + 1]);

    #pragma unroll
    for (int j = 0; j < NKK; j++) {
        int kk = KB + j;
        int ki = kk / 7, kj = kk % 7;
        u64 kd = dup2f(kf[j]);
        const ulonglong2* xp = (const ulonglong2*)(xs + ((py + ki) * HALO + (px + kj)) * PSTR + q * 16);
        ulonglong2 v0 = xp[0], v1 = xp[1], v2 = xp[2], v3 = xp[3];
        fma2(inv2[0], kd, v0.x); fma2(inv2[1], kd, v0.y);
        fma2(inv2[2], kd, v1.x); fma2(inv2[3], kd, v1.y);
        fma2(inv2[4], kd, v2.x); fma2(inv2[5], kd, v2.y);
        fma2(inv2[6], kd, v3.x); fma2(inv2[7], kd, v3.y);
    }
}

__global__ __launch_bounds__(512, 1)
void fused_bottleneck(
    const float* __restrict__ x,
    const float* __restrict__ w_reduce,
    const float* __restrict__ g_r, const float* __restrict__ b_r,
    const float* __restrict__ m_r, const float* __restrict__ v_r,
    const float* __restrict__ w_span, const float* __restrict__ b_span,
    const float* __restrict__ g_i, const float* __restrict__ b_i,
    const float* __restrict__ m_i, const float* __restrict__ v_i,
    const float* __restrict__ w_conv,
    const float* __restrict__ g_c, const float* __restrict__ b_c,
    const float* __restrict__ m_c, const float* __restrict__ v_c,
    const float* __restrict__ w_map, const float* __restrict__ b_map,
    const float* __restrict__ g_m, const float* __restrict__ b_m,
    const float* __restrict__ m_m, const float* __restrict__ v_m,
    float* __restrict__ out)
{
    extern __shared__ float sm[];
    float* xs   = sm + OFF_XS;    // [196][68] halo tile
    float* ts   = sm + OFF_TS;    // [64][20]  reduced features
    float* invP = sm + OFF_INVP;  // [64][68]  h=1 partial involution
    float* x1p  = sm + OFF_X1P;   // [32][132] gelu(bn(inv)), pixel-pair packed f32x2
    float* x0p  = sm + OFF_X0P;   // [32][132] center x, pixel-pair packed f32x2
    float* wrs  = sm + OFF_WRS;   // [16][64]
    float* wspT = sm + OFF_WSPT;  // [4][16][52] span weights transposed+padded
    float* bsps = sm + OFF_BSPS;  // [4][52]   span bias, padded
    float* wcs  = sm + OFF_WCS;   // [128][68] bn-folded w_conv
    float* wms  = sm + OFF_WMS;   // [128][68] bn-folded w_map
    float* bvs  = sm + OFF_BVS;   // [128]     fused bias

    const int tid = threadIdx.x;
    const int gx0 = blockIdx.x * TS;
    const int gy0 = blockIdx.y * TS;
    const int bb  = blockIdx.z;
    const float* xb = x + (size_t)bb * 64 * 96 * 96;

    // ---- Stage halo (zero-padded), plus packed center copy for phase 5 ----
    for (int i = tid; i < NHALO * 64; i += 512) {
        int c = i / NHALO;
        int p = i - c * NHALO;
        int hy = p / HALO;
        int hx = p - hy * HALO;
        int gy = gy0 + hy - 3;
        int gx = gx0 + hx - 3;
        float v = 0.0f;
        if ((unsigned)gy < 96u && (unsigned)gx < 96u)
            v = xb[(c * 96 + gy) * 96 + gx];
        xs[p * PSTR + c] = v;
        int cy = hy - 3, cx = hx - 3;
        if ((unsigned)cy < 8u && (unsigned)cx < 8u)
            x0p[(cy * 4 + (cx >> 1)) * PPSTR + c * 2 + (cx & 1)] = v;
    }
    // ---- Stage weights ----
    for (int i = tid; i < 1024; i += 512) wrs[i] = w_reduce[i];
    for (int i = tid; i < 4 * 16 * 52; i += 512) {
        int q = i / 832;
        int rem = i - q * 832;
        int r = rem / 52;
        int kk = rem - r * 52;
        wspT[i] = (kk < 49) ? w_span[(q * 49 + kk) * 16 + r] : 0.0f;
    }
    for (int i = tid; i < 4 * 52; i += 512) {
        int q = i / 52, kk = i - q * 52;
        bsps[i] = (kk < 49) ? b_span[q * 49 + kk] : 0.0f;
    }
    for (int i = tid; i < 8192; i += 512) {
        int o = i >> 6, c = i & 63;
        float scc = g_c[o] * rsqrtf(v_c[o] + EPS);
        float scm = g_m[o] * rsqrtf(v_m[o] + EPS);
        wcs[o * PSTR + c] = w_conv[i] * scc;
        wms[o * PSTR + c] = w_map[i]  * scm;
    }
    if (tid < 128) {
        float scc = g_c[tid] * rsqrtf(v_c[tid] + EPS);
        float scm = g_m[tid] * rsqrtf(v_m[tid] + EPS);
        bvs[tid] = (b_c[tid] - m_c[tid] * scc)
                 + scm * b_map[tid]
                 + (b_m[tid] - m_m[tid] * scm);
    }
    __syncthreads();

    const int p  = tid & 63;           // pixel in 8x8 tile
    const int py = p >> 3, px = p & 7;
    const int q  = (tid >> 6) & 3;     // involution group (warp-uniform)
    const int h  = tid >> 8;           // tap-range half (warp-uniform)
    const int cpix = (py + 3) * HALO + (px + 3);
    const float4* xs4 = (const float4*)xs;

    // ---- Phase 1: t = relu(bn(w_reduce @ x_center)), 2 rows per thread ----
    {
        const int rr = tid >> 6;       // 0..7 -> rows rr*2, rr*2+1
        float a0 = 0.f, a1 = 0.f;
        const float4* xc4 = xs4 + cpix * (PSTR / 4);
        const float4* wr4 = (const float4*)wrs;
        #pragma unroll
        for (int c4 = 0; c4 < 16; c4++) {
            float4 xv = xc4[c4];
            a0 = dot4acc(wr4[(rr * 2 + 0) * 16 + c4], xv, a0);
            a1 = dot4acc(wr4[(rr * 2 + 1) * 16 + c4], xv, a1);
        }
        float accv[2] = {a0, a1};
        #pragma unroll
        for (int j = 0; j < 2; j++) {
            int r = rr * 2 + j;
            float s = g_r[r] * rsqrtf(v_r[r] + EPS);
            float tv = fmaf(accv[j], s, b_r[r] - m_r[r] * s);
            ts[p * TSTR + r] = fmaxf(tv, 0.0f);
        }
    }
    __syncthreads();

    // ---- Phases 2+3: packed partial span GEMM + partial involution ----
    u64 inv2[8];
    {
        u64 z = dup2f(0.0f);
        #pragma unroll
        for (int j = 0; j < 8; j++) inv2[j] = z;
    }
    if (h == 0)
        inv_partial<0, 28>(wspT, bsps, ts, xs, p, q, py, px, inv2);
    else
        inv_partial<28, 21>(wspT, bsps, ts, xs, p, q, py, px, inv2);

    // h=1 publishes its partial; h=0 combines
    if (h == 1) {
        ulonglong2* dst = (ulonglong2*)(invP + p * PSTR + q * 16);
        #pragma unroll
        for (int j2 = 0; j2 < 4; j2++) {
            ulonglong2 t; t.x = inv2[j2 * 2]; t.y = inv2[j2 * 2 + 1];
            dst[j2] = t;
        }
    }
    __syncthreads();

    // ---- Phase 4: x1 = gelu(bn_i(inv)) -> packed pair layout (h=0 threads) ----
    if (h == 0) {
        const ulonglong2* src = (const ulonglong2*)(invP + p * PSTR + q * 16);
        float* dst = x1p + (p >> 1) * PPSTR + (p & 1);
        #pragma unroll
        for (int j2 = 0; j2 < 4; j2++) {
            ulonglong2 pr = src[j2];
            u64 s0 = add2(inv2[j2 * 2],     pr.x);
            u64 s1 = add2(inv2[j2 * 2 + 1], pr.y);
            float fv[4];
            unpk2(s0, fv[0], fv[1]);
            unpk2(s1, fv[2], fv[3]);
            #pragma unroll
            for (int k = 0; k < 4; k++) {
                int c = q * 16 + j2 * 4 + k;
                float s = g_i[c] * rsqrtf(v_i[c] + EPS);
                float v = fmaf(fv[k], s, b_i[c] - m_i[c] * s);
                dst[c * 2] = gelu_exact(v);
            }
        }
    }
    __syncthreads();

    // ---- Phase 5: out = gelu(wcs@x1 + wms@x + bias), packed pairs ----
    // thread: 2 outputs (o0,o1) x 4 pixel pairs (8 pixels)
    const int og2 = tid >> 3;   // 0..63
    const int pg  = tid & 7;
    const int o0 = og2 * 2, o1 = o0 + 1;

    u64 acc0[4], acc1[4];
    {
        u64 bv0 = dup2f(bvs[o0]), bv1 = dup2f(bvs[o1]);
        #pragma unroll
        for (int i2 = 0; i2 < 4; i2++) { acc0[i2] = bv0; acc1[i2] = bv1; }
    }
    const ulonglong2* x1b[4];
    const ulonglong2* x0b[4];
    #pragma unroll
    for (int i2 = 0; i2 < 4; i2++) {
        int pr_ = pg + 8 * i2;
        x1b[i2] = (const ulonglong2*)(x1p + pr_ * PPSTR);
        x0b[i2] = (const ulonglong2*)(x0p + pr_ * PPSTR);
    }
    const float4* wcA4 = (const float4*)(wcs + o0 * PSTR);
    const float4* wcB4 = (const float4*)(wcs + o1 * PSTR);
    const float4* wmA4 = (const float4*)(wms + o0 * PSTR);
    const float4* wmB4 = (const float4*)(wms + o1 * PSTR);

    #pragma unroll 2
    for (int c4 = 0; c4 < 16; c4++) {
        float4 wa = wcA4[c4], wb = wcB4[c4];
        float4 na = wmA4[c4], nb = wmB4[c4];
        u64 dA0 = dup2f(wa.x), dA1 = dup2f(wa.y), dA2 = dup2f(wa.z), dA3 = dup2f(wa.w);
        u64 dB0 = dup2f(wb.x), dB1 = dup2f(wb.y), dB2 = dup2f(wb.z), dB3 = dup2f(wb.w);
        u64 eA0 = dup2f(na.x), eA1 = dup2f(na.y), eA2 = dup2f(na.z), eA3 = dup2f(na.w);
        u64 eB0 = dup2f(nb.x), eB1 = dup2f(nb.y), eB2 = dup2f(nb.z), eB3 = dup2f(nb.w);
        #pragma unroll
        for (int i2 = 0; i2 < 4; i2++) {
            ulonglong2 xa = x1b[i2][2 * c4], xb = x1b[i2][2 * c4 + 1];
            ulonglong2 ya = x0b[i2][2 * c4], yb = x0b[i2][2 * c4 + 1];
            fma2(acc0[i2], dA0, xa.x); fma2(acc0[i2], dA1, xa.y);
            fma2(acc0[i2], dA2, xb.x); fma2(acc0[i2], dA3, xb.y);
            fma2(acc0[i2], eA0, ya.x); fma2(acc0[i2], eA1, ya.y);
            fma2(acc0[i2], eA2, yb.x); fma2(acc0[i2], eA3, yb.y);
            fma2(acc1[i2], dB0, xa.x); fma2(acc1[i2], dB1, xa.y);
            fma2(acc1[i2], dB2, xb.x); fma2(acc1[i2], dB3, xb.y);
            fma2(acc1[i2], eB0, ya.x); fma2(acc1[i2], eB1, ya.y);
            fma2(acc1[i2], eB2, yb.x); fma2(acc1[i2], eB3, yb.y);
        }
    }

    // ---- Store (final gelu, float2 per pair) ----
    float* ob = out + (size_t)bb * 128 * 96 * 96;
    #pragma unroll
    for (int i2 = 0; i2 < 4; i2++) {
        int pr_ = pg + 8 * i2;
        int pyy = pr_ >> 2, px2 = pr_ & 3;
        int col = gx0 + 2 * px2;
        float lo, hi;
        unpk2(acc0[i2], lo, hi);
        *(float2*)&ob[(o0 * 96 + gy0 + pyy) * 96 + col] =
            make_float2(gelu_exact(lo), gelu_exact(hi));
        unpk2(acc1[i2], lo, hi);
        *(float2*)&ob[(o1 * 96 + gy0 + pyy) * 96 + col] =
            make_float2(gelu_exact(lo), gelu_exact(hi));
    }
}

extern "C" void kernel_launch(void* const* d_in, const int* in_sizes, int n_in,
                              void* d_out, int out_size) {
    const float* x        = (const float*)d_in[0];
    const float* w_reduce = (const float*)d_in[1];
    const float* g_r      = (const float*)d_in[2];
    const float* b_r      = (const float*)d_in[3];
    const float* m_r      = (const float*)d_in[4];
    const float* v_r      = (const float*)d_in[5];
    const float* w_span   = (const float*)d_in[6];
    const float* b_span   = (const float*)d_in[7];
    const float* g_i      = (const float*)d_in[8];
    const float* b_i      = (const float*)d_in[9];
    const float* m_i      = (const float*)d_in[10];
    const float* v_i      = (const float*)d_in[11];
    const float* w_conv   = (const float*)d_in[12];
    const float* g_c      = (const float*)d_in[13];
    const float* b_c      = (const float*)d_in[14];
    const float* m_c      = (const float*)d_in[15];
    const float* v_c      = (const float*)d_in[16];
    const float* w_map    = (const float*)d_in[17];
    const float* b_map    = (const float*)d_in[18];
    const float* g_m      = (const float*)d_in[19];
    const float* b_m      = (const float*)d_in[20];
    const float* m_m      = (const float*)d_in[21];
    const float* v_m      = (const float*)d_in[22];

    cudaFuncSetAttribute(fused_bottleneck,
                         cudaFuncAttributeMaxDynamicSharedMemorySize, SMEM_BYTES);

    dim3 grid(96 / TS, 96 / TS, 4);
    dim3 block(512);
    fused_bottleneck<<<grid, block, SMEM_BYTES>>>(
        x, w_reduce, g_r, b_r, m_r, v_r, w_span, b_span,
        g_i, b_i, m_i, v_i, w_conv, g_c, b_c, m_c, v_c,
        w_map, b_map, g_m, b_m, m_m, v_m, (float*)d_out);
}

// round 10
// speedup vs baseline: 1.3989x; 1.3989x over previous
#include <cuda_runtime.h>
#include <math.h>

#define EPS 1e-5f
#define TS 8
#define HALO 14          // TS + 6
#define PSTR 68          // per-pixel channel stride in floats (64 + 4 pad)
#define NHALO 196        // 14*14
#define TSTR 20          // ts row stride (16 + 4 pad, float4-aligned)

// smem layout (floats)
#define OFF_XS   0
#define OFF_TS   (OFF_XS   + NHALO * PSTR)     // 13328
#define OFF_X1S  (OFF_TS   + 64 * TSTR)        // +1280
#define OFF_INVP (OFF_X1S  + 64 * PSTR)        // +4352
#define OFF_WRS  (OFF_INVP + 64 * PSTR)        // +4352
#define OFF_WSPT (OFF_WRS  + 1024)
#define OFF_BSPS (OFF_WSPT + 4 * 16 * 52)      // +3328
#define OFF_WCS  (OFF_BSPS + 4 * 52)           // +208
#define OFF_WMS  (OFF_WCS  + 128 * PSTR)       // +8704
#define OFF_BVS  (OFF_WMS  + 128 * PSTR)       // +8704
#define SMEM_FLOATS (OFF_BVS + 128)
#define SMEM_BYTES (SMEM_FLOATS * 4)

__device__ __forceinline__ float dot4acc(float4 w, float4 v, float a) {
    a = fmaf(w.x, v.x, a);
    a = fmaf(w.y, v.y, a);
    a = fmaf(w.z, v.z, a);
    a = fmaf(w.w, v.w, a);
    return a;
}

__device__ __forceinline__ float gelu_exact(float v) {
    return 0.5f * v * (1.0f + erff(v * 0.70710678118654752f));
}

// Partial involution over kernel taps [KB, KB+NKK).
// Builds the kern slice (span GEMM restricted to this tap range) and
// accumulates the partial involution for all 16 channels of group q.
template<int KB, int NKK>
__device__ __forceinline__ void inv_partial(
    const float* __restrict__ wspT, const float* __restrict__ bsps,
    const float* __restrict__ ts, const float4* __restrict__ xs4,
    int p, int q, int py, int px, float* inv)
{
    constexpr int NK4 = (NKK + 3) / 4;
    float kern[NK4 * 4];

    // bias slice (wspT/bsps zero-padded to 52, so over-read of the last
    // float4 is harmless)
    const float4* b4 = (const float4*)bsps + q * 13 + KB / 4;
    #pragma unroll
    for (int j = 0; j < NK4; j++) {
        float4 b = b4[j];
        kern[j * 4 + 0] = b.x; kern[j * 4 + 1] = b.y;
        kern[j * 4 + 2] = b.z; kern[j * 4 + 3] = b.w;
    }

    // span GEMM slice: kern[kk] += sum_r wspT[q][r][kk] * t[r]
    const float4* t4 = (const float4*)(ts + p * TSTR);
    #pragma unroll
    for (int r4 = 0; r4 < 4; r4++) {
        float4 tv = t4[r4];
        float tvals[4] = {tv.x, tv.y, tv.z, tv.w};
        #pragma unroll
        for (int rj = 0; rj < 4; rj++) {
            int r = r4 * 4 + rj;
            const float4* w4 = (const float4*)(wspT + (q * 16 + r) * 52) + KB / 4;
            float t_ = tvals[rj];
            #pragma unroll
            for (int j = 0; j < NK4; j++) {
                float4 w = w4[j];
                kern[j * 4 + 0] = fmaf(w.x, t_, kern[j * 4 + 0]);
                kern[j * 4 + 1] = fmaf(w.y, t_, kern[j * 4 + 1]);
                kern[j * 4 + 2] = fmaf(w.z, t_, kern[j * 4 + 2]);
                kern[j * 4 + 3] = fmaf(w.w, t_, kern[j * 4 + 3]);
            }
        }
    }

    // involution over this tap range, all 16 channels of group q
    #pragma unroll
    for (int j = 0; j < NKK; j++) {
        int kk = KB + j;
        int ki = kk / 7, kj = kk % 7;
        float kv = kern[j];
        const float4* xp = xs4 + ((py + ki) * HALO + (px + kj)) * (PSTR / 4) + q * 4;
        float4 v0 = xp[0], v1 = xp[1], v2 = xp[2], v3 = xp[3];
        inv[0]  = fmaf(kv, v0.x, inv[0]);
        inv[1]  = fmaf(kv, v0.y, inv[1]);
        inv[2]  = fmaf(kv, v0.z, inv[2]);
        inv[3]  = fmaf(kv, v0.w, inv[3]);
        inv[4]  = fmaf(kv, v1.x, inv[4]);
        inv[5]  = fmaf(kv, v1.y, inv[5]);
        inv[6]  = fmaf(kv, v1.z, inv[6]);
        inv[7]  = fmaf(kv, v1.w, inv[7]);
        inv[8]  = fmaf(kv, v2.x, inv[8]);
        inv[9]  = fmaf(kv, v2.y, inv[9]);
        inv[10] = fmaf(kv, v2.z, inv[10]);
        inv[11] = fmaf(kv, v2.w, inv[11]);
        inv[12] = fmaf(kv, v3.x, inv[12]);
        inv[13] = fmaf(kv, v3.y, inv[13]);
        inv[14] = fmaf(kv, v3.z, inv[14]);
        inv[15] = fmaf(kv, v3.w, inv[15]);
    }
}

__global__ __launch_bounds__(512, 1)
void fused_bottleneck(
    const float* __restrict__ x,
    const float* __restrict__ w_reduce,
    const float* __restrict__ g_r, const float* __restrict__ b_r,
    const float* __restrict__ m_r, const float* __restrict__ v_r,
    const float* __restrict__ w_span, const float* __restrict__ b_span,
    const float* __restrict__ g_i, const float* __restrict__ b_i,
    const float* __restrict__ m_i, const float* __restrict__ v_i,
    const float* __restrict__ w_conv,
    const float* __restrict__ g_c, const float* __restrict__ b_c,
    const float* __restrict__ m_c, const float* __restrict__ v_c,
    const float* __restrict__ w_map, const float* __restrict__ b_map,
    const float* __restrict__ g_m, const float* __restrict__ b_m,
    const float* __restrict__ m_m, const float* __restrict__ v_m,
    float* __restrict__ out)
{
    extern __shared__ float sm[];
    float* xs   = sm + OFF_XS;    // [196][68] halo tile
    float* ts   = sm + OFF_TS;    // [64][20]  reduced features
    float* x1s  = sm + OFF_X1S;   // [64][68]  gelu(bn(inv))
    float* invP = sm + OFF_INVP;  // [64][68]  h=1 partial involution
    float* wrs  = sm + OFF_WRS;   // [16][64]
    float* wspT = sm + OFF_WSPT;  // [4][16][52] span weights, transposed+padded
    float* bsps = sm + OFF_BSPS;  // [4][52]   span bias, padded
    float* wcs  = sm + OFF_WCS;   // [128][68] bn-folded w_conv
    float* wms  = sm + OFF_WMS;   // [128][68] bn-folded w_map
    float* bvs  = sm + OFF_BVS;   // [128]     fused bias

    const int tid = threadIdx.x;
    const int gx0 = blockIdx.x * TS;
    const int gy0 = blockIdx.y * TS;
    const int bb  = blockIdx.z;
    const float* xb = x + (size_t)bb * 64 * 96 * 96;

    // ---- Stage halo (zero-padded) ----
    for (int i = tid; i < NHALO * 64; i += 512) {
        int c = i / NHALO;
        int p = i - c * NHALO;
        int hy = p / HALO;
        int hx = p - hy * HALO;
        int gy = gy0 + hy - 3;
        int gx = gx0 + hx - 3;
        float v = 0.0f;
        if ((unsigned)gy < 96u && (unsigned)gx < 96u)
            v = xb[(c * 96 + gy) * 96 + gx];
        xs[p * PSTR + c] = v;
    }
    // ---- Stage weights ----
    for (int i = tid; i < 1024; i += 512) wrs[i] = w_reduce[i];
    for (int i = tid; i < 4 * 16 * 52; i += 512) {
        int q = i / 832;
        int rem = i - q * 832;
        int r = rem / 52;
        int kk = rem - r * 52;
        wspT[i] = (kk < 49) ? w_span[(q * 49 + kk) * 16 + r] : 0.0f;
    }
    for (int i = tid; i < 4 * 52; i += 512) {
        int q = i / 52, kk = i - q * 52;
        bsps[i] = (kk < 49) ? b_span[q * 49 + kk] : 0.0f;
    }
    for (int i = tid; i < 8192; i += 512) {
        int o = i >> 6, c = i & 63;
        float scc = g_c[o] * rsqrtf(v_c[o] + EPS);
        float scm = g_m[o] * rsqrtf(v_m[o] + EPS);
        wcs[o * PSTR + c] = w_conv[i] * scc;
        wms[o * PSTR + c] = w_map[i]  * scm;
    }
    if (tid < 128) {
        float scc = g_c[tid] * rsqrtf(v_c[tid] + EPS);
        float scm = g_m[tid] * rsqrtf(v_m[tid] + EPS);
        bvs[tid] = (b_c[tid] - m_c[tid] * scc)
                 + scm * b_map[tid]
                 + (b_m[tid] - m_m[tid] * scm);
    }
    __syncthreads();

    const int p  = tid & 63;           // pixel in 8x8 tile
    const int py = p >> 3, px = p & 7;
    const int q  = (tid >> 6) & 3;     // involution group (warp-uniform)
    const int h  = tid >> 8;           // tap-range half (warp-uniform)
    const int cpix = (py + 3) * HALO + (px + 3);
    const float4* xs4 = (const float4*)xs;

    // ---- Phase 1: t = relu(bn(w_reduce @ x_center)), 2 rows per thread ----
    {
        const int rr = tid >> 6;       // 0..7 -> rows rr*2, rr*2+1
        float a0 = 0.f, a1 = 0.f;
        const float4* xc4 = xs4 + cpix * (PSTR / 4);
        const float4* wr4 = (const float4*)wrs;
        #pragma unroll
        for (int c4 = 0; c4 < 16; c4++) {
            float4 xv = xc4[c4];
            a0 = dot4acc(wr4[(rr * 2 + 0) * 16 + c4], xv, a0);
            a1 = dot4acc(wr4[(rr * 2 + 1) * 16 + c4], xv, a1);
        }
        float accv[2] = {a0, a1};
        #pragma unroll
        for (int j = 0; j < 2; j++) {
            int r = rr * 2 + j;
            float s = g_r[r] * rsqrtf(v_r[r] + EPS);
            float tv = fmaf(accv[j], s, b_r[r] - m_r[r] * s);
            ts[p * TSTR + r] = fmaxf(tv, 0.0f);
        }
    }
    __syncthreads();

    // ---- Phases 2+3: balanced partial span GEMM + partial involution ----
    float inv[16];
    #pragma unroll
    for (int j = 0; j < 16; j++) inv[j] = 0.0f;
    if (h == 0)
        inv_partial<0, 24>(wspT, bsps, ts, xs4, p, q, py, px, inv);
    else
        inv_partial<24, 25>(wspT, bsps, ts, xs4, p, q, py, px, inv);

    // h=1 publishes its partial; h=0 combines
    if (h == 1) {
        float4* dst = (float4*)(invP + p * PSTR + q * 16);
        #pragma unroll
        for (int j4 = 0; j4 < 4; j4++)
            dst[j4] = make_float4(inv[j4*4+0], inv[j4*4+1], inv[j4*4+2], inv[j4*4+3]);
    }
    __syncthreads();

    // ---- Phase 4: x1 = gelu(bn_i(inv)) -> smem (h=0 threads) ----
    if (h == 0) {
        const float4* src = (const float4*)(invP + p * PSTR + q * 16);
        float4* dst = (float4*)(x1s + p * PSTR + q * 16);
        #pragma unroll
        for (int j4 = 0; j4 < 4; j4++) {
            float4 pr = src[j4];
            float prv[4] = {pr.x, pr.y, pr.z, pr.w};
            float vv[4];
            #pragma unroll
            for (int k = 0; k < 4; k++) {
                int c = q * 16 + j4 * 4 + k;
                float s = g_i[c] * rsqrtf(v_i[c] + EPS);
                float v = fmaf(inv[j4 * 4 + k] + prv[k], s, b_i[c] - m_i[c] * s);
                vv[k] = gelu_exact(v);
            }
            dst[j4] = make_float4(vv[0], vv[1], vv[2], vv[3]);
        }
    }
    __syncthreads();

    // ---- Phase 5: out = gelu(wcs@x1 + wms@x + bias), 4 outputs x 4 pixels ----
    const int og = tid >> 4;   // 0..31 -> outputs og*4..og*4+3
    const int pq = tid & 15;   // pixel group: pixels pq*4..pq*4+3
    const int o0 = og * 4;

    float acc[4][4];
    #pragma unroll
    for (int j = 0; j < 4; j++) {
        float bv = bvs[o0 + j];
        #pragma unroll
        for (int i = 0; i < 4; i++) acc[j][i] = bv;
    }
    int x1o[4], xco[4];
    #pragma unroll
    for (int i = 0; i < 4; i++) {
        int pix = pq * 4 + i;
        int py2 = pix >> 3, px2 = pix & 7;
        x1o[i] = pix * (PSTR / 4);
        xco[i] = ((py2 + 3) * HALO + (px2 + 3)) * (PSTR / 4);
    }
    const float4* x14 = (const float4*)x1s;
    const float4* wcB = (const float4*)(wcs + o0 * PSTR);  // rows via j*(PSTR/4)
    const float4* wmB = (const float4*)(wms + o0 * PSTR);

    #pragma unroll 4
    for (int c4 = 0; c4 < 16; c4++) {
        float4 wc0 = wcB[0 * (PSTR / 4) + c4];
        float4 wc1 = wcB[1 * (PSTR / 4) + c4];
        float4 wc2 = wcB[2 * (PSTR / 4) + c4];
        float4 wc3 = wcB[3 * (PSTR / 4) + c4];
        float4 wm0 = wmB[0 * (PSTR / 4) + c4];
        float4 wm1 = wmB[1 * (PSTR / 4) + c4];
        float4 wm2 = wmB[2 * (PSTR / 4) + c4];
        float4 wm3 = wmB[3 * (PSTR / 4) + c4];
        #pragma unroll
        for (int i = 0; i < 4; i++) {
            float4 xv1 = x14[x1o[i] + c4];
            float4 xv0 = xs4[xco[i] + c4];
            acc[0][i] = dot4acc(wc0, xv1, acc[0][i]);
            acc[1][i] = dot4acc(wc1, xv1, acc[1][i]);
            acc[2][i] = dot4acc(wc2, xv1, acc[2][i]);
            acc[3][i] = dot4acc(wc3, xv1, acc[3][i]);
            acc[0][i] = dot4acc(wm0, xv0, acc[0][i]);
            acc[1][i] = dot4acc(wm1, xv0, acc[1][i]);
            acc[2][i] = dot4acc(wm2, xv0, acc[2][i]);
            acc[3][i] = dot4acc(wm3, xv0, acc[3][i]);
        }
    }

    // ---- Store (final gelu, float4 of 4 consecutive columns) ----
    float* ob = out + (size_t)bb * 128 * 96 * 96;
    const int row = gy0 + (pq >> 1);
    const int col = gx0 + (pq & 1) * 4;
    #pragma unroll
    for (int j = 0; j < 4; j++) {
        int o = o0 + j;
        float4 v = make_float4(gelu_exact(acc[j][0]), gelu_exact(acc[j][1]),
                               gelu_exact(acc[j][2]), gelu_exact(acc[j][3]));
        *(float4*)&ob[(o * 96 + row) * 96 + col] = v;
    }
}

extern "C" void kernel_launch(void* const* d_in, const int* in_sizes, int n_in,
                              void* d_out, int out_size) {
    const float* x        = (const float*)d_in[0];
    const float* w_reduce = (const float*)d_in[1];
    const float* g_r      = (const float*)d_in[2];
    const float* b_r      = (const float*)d_in[3];
    const float* m_r      = (const float*)d_in[4];
    const float* v_r      = (const float*)d_in[5];
    const float* w_span   = (const float*)d_in[6];
    const float* b_span   = (const float*)d_in[7];
    const float* g_i      = (const float*)d_in[8];
    const float* b_i      = (const float*)d_in[9];
    const float* m_i      = (const float*)d_in[10];
    const float* v_i      = (const float*)d_in[11];
    const float* w_conv   = (const float*)d_in[12];
    const float* g_c      = (const float*)d_in[13];
    const float* b_c      = (const float*)d_in[14];
    const float* m_c      = (const float*)d_in[15];
    const float* v_c      = (const float*)d_in[16];
    const float* w_map    = (const float*)d_in[17];
    const float* b_map    = (const float*)d_in[18];
    const float* g_m      = (const float*)d_in[19];
    const float* b_m      = (const float*)d_in[20];
    const float* m_m      = (const float*)d_in[21];
    const float* v_m      = (const float*)d_in[22];

    cudaFuncSetAttribute(fused_bottleneck,
                         cudaFuncAttributeMaxDynamicSharedMemorySize, SMEM_BYTES);

    dim3 grid(96 / TS, 96 / TS, 4);
    dim3 block(512);
    fused_bottleneck<<<grid, block, SMEM_BYTES>>>(
        x, w_reduce, g_r, b_r, m_r, v_r, w_span, b_span,
        g_i, b_i, m_i, v_i, w_conv, g_c, b_c, m_c, v_c,
        w_map, b_map, g_m, b_m, m_m, v_m, (float*)d_out);
}

// round 11
// speedup vs baseline: 1.8109x; 1.2945x over previous
#include <cuda_runtime.h>
#include <math.h>

#define EPS 1e-5f
#define TS 8
#define HALO 14          // TS + 6
#define PSTR 68          // per-pixel channel stride in floats (64 + 4 pad)
#define NHALO 196        // 14*14
#define TSTR 20          // ts row stride (16 + 4 pad, float4-aligned)

// smem layout (floats)
#define OFF_XS   0
#define OFF_TS   (OFF_XS   + NHALO * PSTR)     // 13328
#define OFF_X1S  (OFF_TS   + 64 * TSTR)        // +1280
#define OFF_INVP (OFF_X1S  + 64 * PSTR)        // +4352
#define OFF_WRS  (OFF_INVP + 64 * PSTR)        // +4352
#define OFF_WSPT (OFF_WRS  + 1024)
#define OFF_BSPS (OFF_WSPT + 4 * 16 * 52)      // +3328
#define OFF_WCS  (OFF_BSPS + 4 * 52)           // +208
#define OFF_WMS  (OFF_WCS  + 128 * PSTR)       // +8704
#define OFF_BVS  (OFF_WMS  + 128 * PSTR)       // +8704
#define SMEM_FLOATS (OFF_BVS + 128)
#define SMEM_BYTES (SMEM_FLOATS * 4)

__device__ __forceinline__ float dot4acc(float4 w, float4 v, float a) {
    a = fmaf(w.x, v.x, a);
    a = fmaf(w.y, v.y, a);
    a = fmaf(w.z, v.z, a);
    a = fmaf(w.w, v.w, a);
    return a;
}

__device__ __forceinline__ float gelu_exact(float v) {
    return 0.5f * v * (1.0f + erff(v * 0.70710678118654752f));
}

// Partial involution over kernel taps [KB, KB+NKK).
template<int KB, int NKK>
__device__ __forceinline__ void inv_partial(
    const float* __restrict__ wspT, const float* __restrict__ bsps,
    const float* __restrict__ ts, const float4* __restrict__ xs4,
    int p, int q, int py, int px, float* inv)
{
    constexpr int NK4 = (NKK + 3) / 4;
    float kern[NK4 * 4];

    // bias slice (padded to 52, over-read harmless)
    const float4* b4 = (const float4*)bsps + q * 13 + KB / 4;
    #pragma unroll
    for (int j = 0; j < NK4; j++) {
        float4 b = b4[j];
        kern[j * 4 + 0] = b.x; kern[j * 4 + 1] = b.y;
        kern[j * 4 + 2] = b.z; kern[j * 4 + 3] = b.w;
    }

    // span GEMM slice: kern[kk] += sum_r wspT[q][r][kk] * t[r]
    const float4* t4 = (const float4*)(ts + p * TSTR);
    #pragma unroll
    for (int r4 = 0; r4 < 4; r4++) {
        float4 tv = t4[r4];
        float tvals[4] = {tv.x, tv.y, tv.z, tv.w};
        #pragma unroll
        for (int rj = 0; rj < 4; rj++) {
            int r = r4 * 4 + rj;
            const float4* w4 = (const float4*)(wspT + (q * 16 + r) * 52) + KB / 4;
            float t_ = tvals[rj];
            #pragma unroll
            for (int j = 0; j < NK4; j++) {
                float4 w = w4[j];
                kern[j * 4 + 0] = fmaf(w.x, t_, kern[j * 4 + 0]);
                kern[j * 4 + 1] = fmaf(w.y, t_, kern[j * 4 + 1]);
                kern[j * 4 + 2] = fmaf(w.z, t_, kern[j * 4 + 2]);
                kern[j * 4 + 3] = fmaf(w.w, t_, kern[j * 4 + 3]);
            }
        }
    }

    // involution over this tap range, all 16 channels of group q
    #pragma unroll
    for (int j = 0; j < NKK; j++) {
        int kk = KB + j;
        int ki = kk / 7, kj = kk % 7;
        float kv = kern[j];
        const float4* xp = xs4 + ((py + ki) * HALO + (px + kj)) * (PSTR / 4) + q * 4;
        float4 v0 = xp[0], v1 = xp[1], v2 = xp[2], v3 = xp[3];
        inv[0]  = fmaf(kv, v0.x, inv[0]);
        inv[1]  = fmaf(kv, v0.y, inv[1]);
        inv[2]  = fmaf(kv, v0.z, inv[2]);
        inv[3]  = fmaf(kv, v0.w, inv[3]);
        inv[4]  = fmaf(kv, v1.x, inv[4]);
        inv[5]  = fmaf(kv, v1.y, inv[5]);
        inv[6]  = fmaf(kv, v1.z, inv[6]);
        inv[7]  = fmaf(kv, v1.w, inv[7]);
        inv[8]  = fmaf(kv, v2.x, inv[8]);
        inv[9]  = fmaf(kv, v2.y, inv[9]);
        inv[10] = fmaf(kv, v2.z, inv[10]);
        inv[11] = fmaf(kv, v2.w, inv[11]);
        inv[12] = fmaf(kv, v3.x, inv[12]);
        inv[13] = fmaf(kv, v3.y, inv[13]);
        inv[14] = fmaf(kv, v3.z, inv[14]);
        inv[15] = fmaf(kv, v3.w, inv[15]);
    }
}

__global__ __launch_bounds__(512, 1)
void fused_bottleneck(
    const float* __restrict__ x,
    const float* __restrict__ w_reduce,
    const float* __restrict__ g_r, const float* __restrict__ b_r,
    const float* __restrict__ m_r, const float* __restrict__ v_r,
    const float* __restrict__ w_span, const float* __restrict__ b_span,
    const float* __restrict__ g_i, const float* __restrict__ b_i,
    const float* __restrict__ m_i, const float* __restrict__ v_i,
    const float* __restrict__ w_conv,
    const float* __restrict__ g_c, const float* __restrict__ b_c,
    const float* __restrict__ m_c, const float* __restrict__ v_c,
    const float* __restrict__ w_map, const float* __restrict__ b_map,
    const float* __restrict__ g_m, const float* __restrict__ b_m,
    const float* __restrict__ m_m, const float* __restrict__ v_m,
    float* __restrict__ out)
{
    extern __shared__ float sm[];
    float* xs   = sm + OFF_XS;    // [196][68] halo tile
    float* ts   = sm + OFF_TS;    // [64][20]  reduced features
    float* x1s  = sm + OFF_X1S;   // [64][68]  gelu(bn(inv))
    float* invP = sm + OFF_INVP;  // [64][68]  h=1 partial involution
    float* wrs  = sm + OFF_WRS;   // [16][64]
    float* wspT = sm + OFF_WSPT;  // [4][16][52] span weights, transposed+padded
    float* bsps = sm + OFF_BSPS;  // [4][52]   span bias, padded
    float* wcs  = sm + OFF_WCS;   // [128][68] bn-folded w_conv
    float* wms  = sm + OFF_WMS;   // [128][68] bn-folded w_map
    float* bvs  = sm + OFF_BVS;   // [128]     fused bias

    const int tid = threadIdx.x;
    const int gx0 = blockIdx.x * TS;
    const int gy0 = blockIdx.y * TS;
    const int bb  = blockIdx.z;
    const float* xb = x + (size_t)bb * 64 * 96 * 96;

    // ---- Stage halo (zero-padded) ----
    for (int i = tid; i < NHALO * 64; i += 512) {
        int c = i / NHALO;
        int p = i - c * NHALO;
        int hy = p / HALO;
        int hx = p - hy * HALO;
        int gy = gy0 + hy - 3;
        int gx = gx0 + hx - 3;
        float v = 0.0f;
        if ((unsigned)gy < 96u && (unsigned)gx < 96u)
            v = xb[(c * 96 + gy) * 96 + gx];
        xs[p * PSTR + c] = v;
    }
    // ---- Stage weights ----
    for (int i = tid; i < 1024; i += 512) wrs[i] = w_reduce[i];
    for (int i = tid; i < 4 * 16 * 52; i += 512) {
        int q = i / 832;
        int rem = i - q * 832;
        int r = rem / 52;
        int kk = rem - r * 52;
        wspT[i] = (kk < 49) ? w_span[(q * 49 + kk) * 16 + r] : 0.0f;
    }
    for (int i = tid; i < 4 * 52; i += 512) {
        int q = i / 52, kk = i - q * 52;
        bsps[i] = (kk < 49) ? b_span[q * 49 + kk] : 0.0f;
    }
    for (int i = tid; i < 8192; i += 512) {
        int o = i >> 6, c = i & 63;
        float scc = g_c[o] * rsqrtf(v_c[o] + EPS);
        float scm = g_m[o] * rsqrtf(v_m[o] + EPS);
        wcs[o * PSTR + c] = w_conv[i] * scc;
        wms[o * PSTR + c] = w_map[i]  * scm;
    }
    if (tid < 128) {
        float scc = g_c[tid] * rsqrtf(v_c[tid] + EPS);
        float scm = g_m[tid] * rsqrtf(v_m[tid] + EPS);
        bvs[tid] = (b_c[tid] - m_c[tid] * scc)
                 + scm * b_map[tid]
                 + (b_m[tid] - m_m[tid] * scm);
    }
    __syncthreads();

    const int p  = tid & 63;           // pixel in 8x8 tile
    const int py = p >> 3, px = p & 7;
    const int q  = (tid >> 6) & 3;     // involution group (warp-uniform)
    const int h  = tid >> 8;           // tap-range half (warp-uniform)
    const int cpix = (py + 3) * HALO + (px + 3);
    const float4* xs4 = (const float4*)xs;

    // ---- Phase 1: t = relu(bn(w_reduce @ x_center)), 2 rows per thread ----
    {
        const int rr = tid >> 6;       // 0..7 -> rows rr*2, rr*2+1
        float a0 = 0.f, a1 = 0.f;
        const float4* xc4 = xs4 + cpix * (PSTR / 4);
        const float4* wr4 = (const float4*)wrs;
        #pragma unroll
        for (int c4 = 0; c4 < 16; c4++) {
            float4 xv = xc4[c4];
            a0 = dot4acc(wr4[(rr * 2 + 0) * 16 + c4], xv, a0);
            a1 = dot4acc(wr4[(rr * 2 + 1) * 16 + c4], xv, a1);
        }
        float accv[2] = {a0, a1};
        #pragma unroll
        for (int j = 0; j < 2; j++) {
            int r = rr * 2 + j;
            float s = g_r[r] * rsqrtf(v_r[r] + EPS);
            float tv = fmaf(accv[j], s, b_r[r] - m_r[r] * s);
            ts[p * TSTR + r] = fmaxf(tv, 0.0f);
        }
    }
    __syncthreads();

    // ---- Phases 2+3: balanced partial span GEMM + partial involution ----
    float inv[16];
    #pragma unroll
    for (int j = 0; j < 16; j++) inv[j] = 0.0f;
    if (h == 0)
        inv_partial<0, 24>(wspT, bsps, ts, xs4, p, q, py, px, inv);
    else
        inv_partial<24, 25>(wspT, bsps, ts, xs4, p, q, py, px, inv);

    // h=1 publishes its partial; h=0 combines
    if (h == 1) {
        float4* dst = (float4*)(invP + p * PSTR + q * 16);
        #pragma unroll
        for (int j4 = 0; j4 < 4; j4++)
            dst[j4] = make_float4(inv[j4*4+0], inv[j4*4+1], inv[j4*4+2], inv[j4*4+3]);
    }
    __syncthreads();

    // ---- Phase 4: x1 = gelu(bn_i(inv)) -> smem (h=0 threads) ----
    if (h == 0) {
        const float4* src = (const float4*)(invP + p * PSTR + q * 16);
        float4* dst = (float4*)(x1s + p * PSTR + q * 16);
        #pragma unroll
        for (int j4 = 0; j4 < 4; j4++) {
            float4 pr = src[j4];
            float prv[4] = {pr.x, pr.y, pr.z, pr.w};
            float vv[4];
            #pragma unroll
            for (int k = 0; k < 4; k++) {
                int c = q * 16 + j4 * 4 + k;
                float s = g_i[c] * rsqrtf(v_i[c] + EPS);
                float v = fmaf(inv[j4 * 4 + k] + prv[k], s, b_i[c] - m_i[c] * s);
                vv[k] = gelu_exact(v);
            }
            dst[j4] = make_float4(vv[0], vv[1], vv[2], vv[3]);
        }
    }
    __syncthreads();

    // ---- Phase 5: out = gelu(wcs@x1 + wms@x + bias) ----
    // 4 outputs x 4 STRIDED pixels per thread: pixels {pg, pg+16, pg+32, pg+48}
    // -> inter-lane pixel stride stays 1 (68 words = 4 banks): conflict-free.
    const int og = tid >> 4;   // 0..31 -> outputs og*4..og*4+3
    const int pg = tid & 15;   // base pixel
    const int o0 = og * 4;

    float acc[4][4];
    #pragma unroll
    for (int j = 0; j < 4; j++) {
        float bv = bvs[o0 + j];
        #pragma unroll
        for (int i = 0; i < 4; i++) acc[j][i] = bv;
    }
    int x1o[4], xco[4];
    #pragma unroll
    for (int i = 0; i < 4; i++) {
        int pix = pg + 16 * i;
        int py2 = pix >> 3, px2 = pix & 7;
        x1o[i] = pix * (PSTR / 4);
        xco[i] = ((py2 + 3) * HALO + (px2 + 3)) * (PSTR / 4);
    }
    const float4* x14 = (const float4*)x1s;
    const float4* wcB = (const float4*)(wcs + o0 * PSTR);
    const float4* wmB = (const float4*)(wms + o0 * PSTR);

    #pragma unroll 4
    for (int c4 = 0; c4 < 16; c4++) {
        float4 wc0 = wcB[0 * (PSTR / 4) + c4];
        float4 wc1 = wcB[1 * (PSTR / 4) + c4];
        float4 wc2 = wcB[2 * (PSTR / 4) + c4];
        float4 wc3 = wcB[3 * (PSTR / 4) + c4];
        float4 wm0 = wmB[0 * (PSTR / 4) + c4];
        float4 wm1 = wmB[1 * (PSTR / 4) + c4];
        float4 wm2 = wmB[2 * (PSTR / 4) + c4];
        float4 wm3 = wmB[3 * (PSTR / 4) + c4];
        #pragma unroll
        for (int i = 0; i < 4; i++) {
            float4 xv1 = x14[x1o[i] + c4];
            float4 xv0 = xs4[xco[i] + c4];
            acc[0][i] = dot4acc(wc0, xv1, acc[0][i]);
            acc[1][i] = dot4acc(wc1, xv1, acc[1][i]);
            acc[2][i] = dot4acc(wc2, xv1, acc[2][i]);
            acc[3][i] = dot4acc(wc3, xv1, acc[3][i]);
            acc[0][i] = dot4acc(wm0, xv0, acc[0][i]);
            acc[1][i] = dot4acc(wm1, xv0, acc[1][i]);
            acc[2][i] = dot4acc(wm2, xv0, acc[2][i]);
            acc[3][i] = dot4acc(wm3, xv0, acc[3][i]);
        }
    }

    // ---- Store (final gelu) ----
    float* ob = out + (size_t)bb * 128 * 96 * 96;
    const int pybase = pg >> 3, pxs = pg & 7;
    #pragma unroll
    for (int j = 0; j < 4; j++) {
        int o = o0 + j;
        #pragma unroll
        for (int i = 0; i < 4; i++) {
            int pyy = pybase + 2 * i;
            ob[(o * 96 + gy0 + pyy) * 96 + gx0 + pxs] = gelu_exact(acc[j][i]);
        }
    }
}

extern "C" void kernel_launch(void* const* d_in, const int* in_sizes, int n_in,
                              void* d_out, int out_size) {
    const float* x        = (const float*)d_in[0];
    const float* w_reduce = (const float*)d_in[1];
    const float* g_r      = (const float*)d_in[2];
    const float* b_r      = (const float*)d_in[3];
    const float* m_r      = (const float*)d_in[4];
    const float* v_r      = (const float*)d_in[5];
    const float* w_span   = (const float*)d_in[6];
    const float* b_span   = (const float*)d_in[7];
    const float* g_i      = (const float*)d_in[8];
    const float* b_i      = (const float*)d_in[9];
    const float* m_i      = (const float*)d_in[10];
    const float* v_i      = (const float*)d_in[11];
    const float* w_conv   = (const float*)d_in[12];
    const float* g_c      = (const float*)d_in[13];
    const float* b_c      = (const float*)d_in[14];
    const float* m_c      = (const float*)d_in[15];
    const float* v_c      = (const float*)d_in[16];
    const float* w_map    = (const float*)d_in[17];
    const float* b_map    = (const float*)d_in[18];
    const float* g_m      = (const float*)d_in[19];
    const float* b_m      = (const float*)d_in[20];
    const float* m_m      = (const float*)d_in[21];
    const float* v_m      = (const float*)d_in[22];

    cudaFuncSetAttribute(fused_bottleneck,
                         cudaFuncAttributeMaxDynamicSharedMemorySize, SMEM_BYTES);

    dim3 grid(96 / TS, 96 / TS, 4);
    dim3 block(512);
    fused_bottleneck<<<grid, block, SMEM_BYTES>>>(
        x, w_reduce, g_r, b_r, m_r, v_r, w_span, b_span,
        g_i, b_i, m_i, v_i, w_conv, g_c, b_c, m_c, v_c,
        w_map, b_map, g_m, b_m, m_m, v_m, (float*)d_out);
}